// round 11
// baseline (speedup 1.0000x reference)
#include <cuda_runtime.h>
#include <cuda_bf16.h>
#include <stdint.h>

// ---------------------------------------------------------------------------
// Hodge1LapEdgeEncoder
//
// Output (float32): [0,P) idx rows | [P,2P) idx cols | [2P,2P+P*D) dense vals
//   dense[slot,:] = padding + sum_{e: slot(e)==slot} (edge_attr[e] + pestat[e,0]*fc_w)
//   slot(e) = u*n + (v%n),  u = ei[0,e], v = ei[1,e]
//
// Tier 1: software pipeline over S row-chunks of the dense region.
//   Stage kernel = [scatter blocks for chunk i-1] + [init blocks for chunk i]
//   (+ idx blocks in stage 0). Disjoint outputs inside one kernel -> the
//   latency-bound scatter overlaps the LTS-bound init stream.
// Tier 2: fully generic scalar path.
// ---------------------------------------------------------------------------

#define TB 256
#define IPT 4            // float4 stores per init thread

__device__ __forceinline__ void red_add_v4(float* dst, float4 r)
{
#if __CUDA_ARCH__ >= 900
    asm volatile("red.global.add.v4.f32 [%0], {%1, %2, %3, %4};"
                 :: "l"(dst), "f"(r.x), "f"(r.y), "f"(r.z), "f"(r.w)
                 : "memory");
#else
    atomicAdd(dst + 0, r.x); atomicAdd(dst + 1, r.y);
    atomicAdd(dst + 2, r.z); atomicAdd(dst + 3, r.w);
#endif
}

// ===========================================================================
// Tier 1 pipeline stage kernel. Block roles by bid:
//   [0, scatBlocks)                 scatter edges with uLo <= u < uHi
//   [scatBlocks, +initBlocks)       padding-init of dense float4 range
//   [scatBlocks+initBlocks, +idx)   idx pattern
// ===========================================================================
__global__ void k_stage(float* __restrict__ out, long long P,
                        const int*    __restrict__ ei,      // [2, E]
                        const float*  __restrict__ pestat,  // [E, K]
                        const float4* __restrict__ ea4,     // [E, D4]
                        const float4* __restrict__ w4,      // [D4]
                        const float4* __restrict__ pad4,    // [D4]
                        float* __restrict__ val,            // dense base
                        int E, int K, int s4, int sn,
                        int uLo, int uHi,
                        long long initBase4, long long initCount4,
                        int scatBlocks, int initBlocks)
{
    const int tid = threadIdx.x;
    const int bid = blockIdx.x;

    if (bid < scatBlocks) {
        // ---- scatter (R4-proven body + row-range filter) ----
        int t = bid * TB + tid;
        int tot = E << s4;
        if (t >= tot) return;
        int e = t >> s4;
        int c = t & ((1 << s4) - 1);

        int u = __ldg(&ei[e]);
        if (u < uLo || u >= uHi) return;
        int rv = __ldg(&ei[E + e]) & ((1 << sn) - 1);

        float  p = __ldg(&pestat[(long long)e * K]);
        float4 a = __ldg(&ea4[((long long)e << s4) + c]);
        float4 w = __ldg(&w4[c]);
        float4 rr = make_float4(a.x + p * w.x, a.y + p * w.y,
                                a.z + p * w.z, a.w + p * w.w);

        long long slot = ((long long)u << sn) | rv;
        red_add_v4(val + (slot << (s4 + 2)) + (c << 2), rr);
        return;
    }

    if (bid < scatBlocks + initBlocks) {
        // ---- padding-broadcast init over [initBase4, initBase4+initCount4) ----
        // initBase4 is D4-aligned and TB*IPT | stride => column = tid & (D4-1).
        const int D4 = 1 << s4;
        float4* val4 = ((float4*)val) + initBase4;
        long long v = (long long)(bid - scatBlocks) * (TB * IPT) + tid;
        float4 pv = __ldg(&pad4[tid & (D4 - 1)]);
        #pragma unroll
        for (int k = 0; k < IPT; k++) {
            long long idx = v + (long long)k * TB;
            if (idx < initCount4) val4[idx] = pv;
        }
        return;
    }

    // ---- idx pattern, float4-vectorized (n % 4 == 0 by host guard) ----
    long long P4 = P >> 2;
    long long t = (long long)(bid - scatBlocks - initBlocks) * TB + tid;
    if (t >= P4) return;
    long long q = t << 2;
    int nm1  = (1 << sn) - 1;
    long long nnm1 = ((long long)1 << (2 * sn)) - 1;
    int b   = (int)(q >> (2 * sn));
    int rem = (int)(q & nnm1);
    int i   = rem >> sn;
    int j   = rem & nm1;
    float rv = (float)((b << sn) + i);
    float cv = (float)((b << sn) + j);
    ((float4*)out)[t]       = make_float4(rv, rv, rv, rv);
    ((float4*)(out + P))[t] = make_float4(cv, cv + 1.f, cv + 2.f, cv + 3.f);
}

// ===========================================================================
// Tier 2: fully generic fallbacks.
// ===========================================================================
__global__ void k_init_fused_s(float* __restrict__ out, const float* __restrict__ pad,
                               long long P, int n, int D)
{
    long long totalI = P;
    long long tot = P + P * (long long)D;
    float* val = out + 2 * P;
    long long stride = (long long)gridDim.x * blockDim.x;
    for (long long t = (long long)blockIdx.x * blockDim.x + threadIdx.x;
         t < tot; t += stride) {
        if (t < totalI) {
            long long nn = (long long)n * n;
            int b   = (int)(t / nn);
            int rem = (int)(t - (long long)b * nn);
            int i   = rem / n;
            int j   = rem - i * n;
            out[t]     = (float)(b * n + i);
            out[P + t] = (float)(b * n + j);
        } else {
            long long v = t - totalI;
            val[v] = __ldg(&pad[(int)(v % D)]);
        }
    }
}

__global__ void k_scatter_s(const int* __restrict__ ei, const float* __restrict__ pestat,
                            const float* __restrict__ ea, const float* __restrict__ w,
                            float* __restrict__ val, int E, int K, int D, int n)
{
    long long tot = (long long)E * D;
    long long stride = (long long)gridDim.x * blockDim.x;
    for (long long t = (long long)blockIdx.x * blockDim.x + threadIdx.x;
         t < tot; t += stride) {
        int e = (int)(t / D);
        int d = (int)(t - (long long)e * D);
        int u = __ldg(&ei[e]);
        int v = __ldg(&ei[E + e]);
        int g  = u / n;
        int ru = u - g * n;
        int rv = v % n;
        float p = __ldg(&pestat[(long long)e * K]);
        float x = ea[(long long)e * D + d] + p * __ldg(&w[d]);
        long long base = (((long long)g * n + ru) * n + rv) * (long long)D + d;
        atomicAdd(val + base, x);
    }
}

// ===========================================================================

static inline bool is_pow2(int x) { return x > 0 && (x & (x - 1)) == 0; }
static inline int  ilog2(int x)   { int s = 0; while ((1 << s) < x) s++; return s; }
static inline int grid_for(long long work, int tb)
{
    long long g = (work + tb - 1) / tb;
    if (g > 1048576) g = 1048576;
    if (g < 1) g = 1;
    return (int)g;
}

extern "C" void kernel_launch(void* const* d_in, const int* in_sizes, int n_in,
                              void* d_out, int out_size)
{
    // metadata order: edge_index, pestat, edge_attr, batch, fc_w, padding
    const int*   ei     = (const int*)  d_in[0];
    const float* pestat = (const float*)d_in[1];
    const float* ea     = (const float*)d_in[2];
    const float* fc_w   = (const float*)d_in[4];
    const float* pad    = (const float*)d_in[5];

    const int E = in_sizes[0] / 2;
    const int K = in_sizes[1] / E;
    const int D = in_sizes[2] / E;
    const int N = in_sizes[3];                            // dense rows = B*n
    const long long P = (long long)out_size / (D + 2);    // slots = B*n*n
    const int n = (int)(P / N);

    float* out = (float*)d_out;
    float* val = out + 2 * P;
    const int D4 = D / 4;

    const bool pow2ok = (D % 4 == 0) && (n % 4 == 0) &&
                        is_pow2(n) && is_pow2(D4) && D4 <= 256 &&
                        ((long long)E * D4 < (1LL << 31));

    if (pow2ok) {
        const int sn = ilog2(n);
        const int s4 = ilog2(D4);
        const int idxBlocks  = (int)(((P >> 2) + TB - 1) / TB);
        const int scatFull   = (int)(((long long)(E << s4) + TB - 1) / TB);

        const int S = (N >= 4) ? 4 : 1;                   // pipeline depth
        const int chunkRows = (N + S - 1) / S;

        for (int s = 0; s <= S; s++) {
            // scatter range = chunk s-1 ; init range = chunk s
            int suLo = (s - 1) * chunkRows;
            int suHi = s * chunkRows; if (suHi > N) suHi = N;
            bool doScat = (s >= 1) && (suLo < suHi);

            int iuLo = s * chunkRows; if (iuLo > N) iuLo = N;
            int iuHi = (s + 1) * chunkRows; if (iuHi > N) iuHi = N;
            bool doInit = (s < S) && (iuLo < iuHi);

            long long initBase4  = (long long)iuLo * n * D4;
            long long initCount4 = (long long)(iuHi - iuLo) * n * D4;

            int scatBlocks = doScat ? scatFull : 0;
            int initBlocks = doInit
                ? (int)((initCount4 + (long long)TB * IPT - 1) / ((long long)TB * IPT))
                : 0;
            int idxB = (s == 0) ? idxBlocks : 0;

            int grid = scatBlocks + initBlocks + idxB;
            if (grid == 0) continue;

            k_stage<<<grid, TB>>>(out, P, ei, pestat,
                                  (const float4*)ea, (const float4*)fc_w,
                                  (const float4*)pad, val,
                                  E, K, s4, sn,
                                  doScat ? suLo : 0, doScat ? suHi : 0,
                                  initBase4, doInit ? initCount4 : 0,
                                  scatBlocks, initBlocks);
        }
    } else {
        long long tot = P + P * (long long)D;
        k_init_fused_s<<<grid_for(tot, TB), TB>>>(out, pad, P, n, D);
        long long st = (long long)E * D;
        k_scatter_s<<<grid_for(st, TB), TB>>>(ei, pestat, ea, fc_w, val,
                                              E, K, D, n);
    }
}

// round 12
// speedup vs baseline: 1.1493x; 1.1493x over previous
#include <cuda_runtime.h>
#include <cuda_bf16.h>
#include <stdint.h>

// ---------------------------------------------------------------------------
// Hodge1LapEdgeEncoder
//
// Output (float32): [0,P) idx rows | [P,2P) idx cols | [2P,2P+P*D) dense vals
//   dense[slot,:] = padding + sum_{e: slot(e)==slot} (edge_attr[e] + pestat[e,0]*fc_w)
//   slot(e) = u*n + (v%n),  u = ei[0,e], v = ei[1,e]
//
// Tier 1 (first-edge-owns-slot):
//   K1: per-edge pos = atomicAdd(cnt[slot]) (+ idx pattern blocks).
//   K2: ONE launch, disjoint writes:
//        edge blocks: pos==0 edge plain-stores padding+value over its slot.
//        init blocks: padding-store ONLY cnt==0 slots; reset cnt.
//   K3: pos>0 edges red.v4 onto the already-stored slots.
// Tier 2: R10 proven path (init4 + idx/scatter).  Tier 3: generic scalar.
// ---------------------------------------------------------------------------

#define TB 256
#define CNT_MAX (1 << 20)              // max slots (P)
#define EDGE_MAX (1 << 17)             // max edges (E)

__device__ int g_cnt[CNT_MAX];         // zero .bss; K2 init blocks reset
__device__ int g_pos[EDGE_MAX];        // fully overwritten each K1

__device__ __forceinline__ void red_add_v4(float* dst, float4 r)
{
#if __CUDA_ARCH__ >= 900
    asm volatile("red.global.add.v4.f32 [%0], {%1, %2, %3, %4};"
                 :: "l"(dst), "f"(r.x), "f"(r.y), "f"(r.z), "f"(r.w)
                 : "memory");
#else
    atomicAdd(dst + 0, r.x); atomicAdd(dst + 1, r.y);
    atomicAdd(dst + 2, r.z); atomicAdd(dst + 3, r.w);
#endif
}

// ===========================================================================
// Tier 1 K1: edge binning (leading blocks) + idx pattern (trailing blocks).
// ===========================================================================
__global__ void k_bin_idx(const int* __restrict__ ei, int E,
                          float* __restrict__ out, long long P,
                          int sn, int binBlocks)
{
    const int tid = threadIdx.x;
    const int bid = blockIdx.x;

    if (bid < binBlocks) {
        int e = bid * TB + tid;
        if (e >= E) return;
        int u  = __ldg(&ei[e]);
        int rv = __ldg(&ei[E + e]) & ((1 << sn) - 1);
        int slot = (u << sn) | rv;
        g_pos[e] = atomicAdd(&g_cnt[slot], 1);
        return;
    }
    // ---- idx pattern, float4-vectorized (n % 4 == 0 by host guard) ----
    long long P4 = P >> 2;
    long long t = (long long)(bid - binBlocks) * TB + tid;
    if (t >= P4) return;
    long long q = t << 2;
    int nm1  = (1 << sn) - 1;
    long long nnm1 = ((long long)1 << (2 * sn)) - 1;
    int b   = (int)(q >> (2 * sn));
    int rem = (int)(q & nnm1);
    int i   = rem >> sn;
    int j   = rem & nm1;
    float rv = (float)((b << sn) + i);
    float cv = (float)((b << sn) + j);
    ((float4*)out)[t]       = make_float4(rv, rv, rv, rv);
    ((float4*)(out + P))[t] = make_float4(cv, cv + 1.f, cv + 2.f, cv + 3.f);
}

// ===========================================================================
// Tier 1 K2: edge first-store blocks (leading) + clean-slot init blocks.
// Writes are disjoint (dirty slots only by edges, clean slots only by init),
// so no intra-kernel ordering is required.
// ===========================================================================
__global__ void k_dense(float4* __restrict__ val4,
                        const int*    __restrict__ ei,      // [2, E]
                        const float*  __restrict__ pestat,  // [E, K]
                        const float4* __restrict__ ea4,     // [E, D4]
                        const float4* __restrict__ w4,      // [D4]
                        const float4* __restrict__ pad4,    // [D4]
                        int E, int K, int s4, int sn,
                        long long V4, int edgeBlocks)
{
    const int tid = threadIdx.x;
    const int bid = blockIdx.x;
    const int D4m = (1 << s4) - 1;

    if (bid < edgeBlocks) {
        // ---- first edge of each slot stores padding + its value ----
        int t = bid * TB + tid;
        if (t >= (E << s4)) return;
        int e = t >> s4;
        int c = t & D4m;
        if (g_pos[e] != 0) return;            // only the slot owner stores

        int u  = __ldg(&ei[e]);
        int rv = __ldg(&ei[E + e]) & ((1 << sn) - 1);
        float  p = __ldg(&pestat[(long long)e * K]);
        float4 a = __ldg(&ea4[((long long)e << s4) + c]);
        float4 w = __ldg(&w4[c]);
        float4 pv = __ldg(&pad4[c]);
        float4 acc = make_float4(pv.x + a.x + p * w.x,
                                 pv.y + a.y + p * w.y,
                                 pv.z + a.z + p * w.z,
                                 pv.w + a.w + p * w.w);
        long long slot = ((long long)u << sn) | rv;
        val4[(slot << s4) + c] = acc;
        return;
    }

    // ---- init: padding to clean slots only; reset cnt for next replay ----
    long long v = (long long)(bid - edgeBlocks) * TB + tid;
    if (v >= V4) return;
    int c = tid & D4m;                        // TB % D4 == 0, base aligned
    long long slot = v >> s4;
    int m = g_cnt[slot];                      // coalesced: D4 threads share
    if (m == 0) val4[v] = __ldg(&pad4[c]);
    if (c == 0) g_cnt[slot] = 0;
}

// ===========================================================================
// Tier 1 K3: duplicate edges (pos > 0) red.v4 onto stored slots.
// ===========================================================================
__global__ void k_dups(float* __restrict__ val,
                       const int* __restrict__ ei,
                       const float* __restrict__ pestat,
                       const float4* __restrict__ ea4,
                       const float4* __restrict__ w4,
                       int E, int K, int s4, int sn)
{
    int t = blockIdx.x * TB + threadIdx.x;
    if (t >= (E << s4)) return;
    int e = t >> s4;
    int c = t & ((1 << s4) - 1);
    if (g_pos[e] == 0) return;                // owners already stored

    int u  = __ldg(&ei[e]);
    int rv = __ldg(&ei[E + e]) & ((1 << sn) - 1);
    float  p = __ldg(&pestat[(long long)e * K]);
    float4 a = __ldg(&ea4[((long long)e << s4) + c]);
    float4 w = __ldg(&w4[c]);
    float4 rr = make_float4(a.x + p * w.x, a.y + p * w.y,
                            a.z + p * w.z, a.w + p * w.w);
    long long slot = ((long long)u << sn) | rv;
    red_add_v4(val + (slot << (s4 + 2)) + (c << 2), rr);
}

// ===========================================================================
// Tier 2: R10 proven path (init with IPT stores + idx/scatter kernel).
// ===========================================================================
#define IPT 4

__global__ void k_init4(float4* __restrict__ val4,
                        const float4* __restrict__ pad4,
                        long long V4, int D4)
{
    long long base = (long long)blockIdx.x * (TB * IPT) + threadIdx.x;
    float4 pv = __ldg(&pad4[(int)threadIdx.x & (D4 - 1)]);
    #pragma unroll
    for (int k = 0; k < IPT; k++) {
        long long v = base + (long long)k * TB;
        if (v < V4) val4[v] = pv;
    }
}

__global__ void k_idx_scatter(float* __restrict__ out, long long P,
                              const int* __restrict__ ei,
                              const float* __restrict__ pestat,
                              const float4* __restrict__ ea4,
                              const float4* __restrict__ w4,
                              float* __restrict__ val,
                              int E, int K, int s4, int sn,
                              int idxBlocks)
{
    const int tid = threadIdx.x;
    const int bid = blockIdx.x;

    if (bid < idxBlocks) {
        long long P4 = P >> 2;
        long long t = (long long)bid * TB + tid;
        if (t >= P4) return;
        long long q = t << 2;
        int nm1  = (1 << sn) - 1;
        long long nnm1 = ((long long)1 << (2 * sn)) - 1;
        int b   = (int)(q >> (2 * sn));
        int rem = (int)(q & nnm1);
        int i   = rem >> sn;
        int j   = rem & nm1;
        float rv = (float)((b << sn) + i);
        float cv = (float)((b << sn) + j);
        ((float4*)out)[t]       = make_float4(rv, rv, rv, rv);
        ((float4*)(out + P))[t] = make_float4(cv, cv + 1.f, cv + 2.f, cv + 3.f);
        return;
    }

    int t = (bid - idxBlocks) * TB + tid;
    int tot = E << s4;
    if (t >= tot) return;
    int e = t >> s4;
    int c = t & ((1 << s4) - 1);

    int u  = __ldg(&ei[e]);
    int rv = __ldg(&ei[E + e]) & ((1 << sn) - 1);
    float  p = __ldg(&pestat[(long long)e * K]);
    float4 a = __ldg(&ea4[((long long)e << s4) + c]);
    float4 w = __ldg(&w4[c]);
    float4 rr = make_float4(a.x + p * w.x, a.y + p * w.y,
                            a.z + p * w.z, a.w + p * w.w);
    long long slot = ((long long)u << sn) | rv;
    red_add_v4(val + (slot << (s4 + 2)) + (c << 2), rr);
}

// ===========================================================================
// Tier 3: fully generic fallbacks.
// ===========================================================================
__global__ void k_init_fused_s(float* __restrict__ out, const float* __restrict__ pad,
                               long long P, int n, int D)
{
    long long totalI = P;
    long long tot = P + P * (long long)D;
    float* val = out + 2 * P;
    long long stride = (long long)gridDim.x * blockDim.x;
    for (long long t = (long long)blockIdx.x * blockDim.x + threadIdx.x;
         t < tot; t += stride) {
        if (t < totalI) {
            long long nn = (long long)n * n;
            int b   = (int)(t / nn);
            int rem = (int)(t - (long long)b * nn);
            int i   = rem / n;
            int j   = rem - i * n;
            out[t]     = (float)(b * n + i);
            out[P + t] = (float)(b * n + j);
        } else {
            long long v = t - totalI;
            val[v] = __ldg(&pad[(int)(v % D)]);
        }
    }
}

__global__ void k_scatter_s(const int* __restrict__ ei, const float* __restrict__ pestat,
                            const float* __restrict__ ea, const float* __restrict__ w,
                            float* __restrict__ val, int E, int K, int D, int n)
{
    long long tot = (long long)E * D;
    long long stride = (long long)gridDim.x * blockDim.x;
    for (long long t = (long long)blockIdx.x * blockDim.x + threadIdx.x;
         t < tot; t += stride) {
        int e = (int)(t / D);
        int d = (int)(t - (long long)e * D);
        int u = __ldg(&ei[e]);
        int v = __ldg(&ei[E + e]);
        int g  = u / n;
        int ru = u - g * n;
        int rv = v % n;
        float p = __ldg(&pestat[(long long)e * K]);
        float x = ea[(long long)e * D + d] + p * __ldg(&w[d]);
        long long base = (((long long)g * n + ru) * n + rv) * (long long)D + d;
        atomicAdd(val + base, x);
    }
}

// ===========================================================================

static inline bool is_pow2(int x) { return x > 0 && (x & (x - 1)) == 0; }
static inline int  ilog2(int x)   { int s = 0; while ((1 << s) < x) s++; return s; }
static inline int grid_for(long long work, int tb)
{
    long long g = (work + tb - 1) / tb;
    if (g > 1048576) g = 1048576;
    if (g < 1) g = 1;
    return (int)g;
}

extern "C" void kernel_launch(void* const* d_in, const int* in_sizes, int n_in,
                              void* d_out, int out_size)
{
    // metadata order: edge_index, pestat, edge_attr, batch, fc_w, padding
    const int*   ei     = (const int*)  d_in[0];
    const float* pestat = (const float*)d_in[1];
    const float* ea     = (const float*)d_in[2];
    const float* fc_w   = (const float*)d_in[4];
    const float* pad    = (const float*)d_in[5];

    const int E = in_sizes[0] / 2;
    const int K = in_sizes[1] / E;
    const int D = in_sizes[2] / E;
    const int N = in_sizes[3];                            // dense rows = B*n
    const long long P = (long long)out_size / (D + 2);    // slots = B*n*n
    const int n = (int)(P / N);

    float* out = (float*)d_out;
    float* val = out + 2 * P;
    const int D4 = D / 4;

    const bool pow2ok = (D % 4 == 0) && (n % 4 == 0) &&
                        is_pow2(n) && is_pow2(D4) && D4 <= 256 &&
                        ((long long)E * D4 < (1LL << 31));

    const bool fastok = pow2ok && D4 <= 32 && P <= CNT_MAX && E <= EDGE_MAX &&
                        (long long)P == (long long)N * n;

    if (fastok) {
        const int sn = ilog2(n);
        const int s4 = ilog2(D4);
        const long long V4 = P * (long long)D4;
        const int idxBlocks  = (int)(((P >> 2) + TB - 1) / TB);
        const int binBlocks  = (E + TB - 1) / TB;
        const int edgeBlocks = (int)(((long long)(E << s4) + TB - 1) / TB);
        const int initBlocks = (int)((V4 + TB - 1) / TB);

        // K1: binning (leading) + idx pattern (trailing)
        k_bin_idx<<<binBlocks + idxBlocks, TB>>>(ei, E, out, P, sn, binBlocks);

        // K2: first-edge stores (leading) + clean-slot init (trailing)
        k_dense<<<edgeBlocks + initBlocks, TB>>>((float4*)val, ei, pestat,
                                                 (const float4*)ea,
                                                 (const float4*)fc_w,
                                                 (const float4*)pad,
                                                 E, K, s4, sn, V4, edgeBlocks);

        // K3: duplicate edges red.v4
        k_dups<<<edgeBlocks, TB>>>(val, ei, pestat, (const float4*)ea,
                                   (const float4*)fc_w, E, K, s4, sn);
    } else if (pow2ok) {
        const int sn = ilog2(n);
        const int s4 = ilog2(D4);
        const long long V4 = P * (long long)D4;

        long long initBlocks = (V4 + (long long)TB * IPT - 1) / ((long long)TB * IPT);
        k_init4<<<(int)initBlocks, TB>>>((float4*)val, (const float4*)pad,
                                         V4, D4);

        const int idxBlocks  = (int)(((P >> 2) + TB - 1) / TB);
        const int scatBlocks = (int)(((long long)(E << s4) + TB - 1) / TB);
        k_idx_scatter<<<idxBlocks + scatBlocks, TB>>>(out, P, ei, pestat,
                                                      (const float4*)ea,
                                                      (const float4*)fc_w,
                                                      val, E, K, s4, sn,
                                                      idxBlocks);
    } else {
        long long tot = P + P * (long long)D;
        k_init_fused_s<<<grid_for(tot, TB), TB>>>(out, pad, P, n, D);
        long long st = (long long)E * D;
        k_scatter_s<<<grid_for(st, TB), TB>>>(ei, pestat, ea, fc_w, val,
                                              E, K, D, n);
    }
}

// round 13
// speedup vs baseline: 1.6025x; 1.3944x over previous
#include <cuda_runtime.h>
#include <cuda_bf16.h>
#include <stdint.h>

// ---------------------------------------------------------------------------
// Hodge1LapEdgeEncoder
//
// Output (float32): [0,P) idx rows | [P,2P) idx cols | [2P,2P+P*D) dense vals
//   dense[slot,:] = padding + sum_{e: slot(e)==slot} (edge_attr[e] + pestat[e,0]*fc_w)
//   slot(e) = u*n + (v%n),  u = ei[0,e], v = ei[1,e]
//
// Tier 1 (R10 skeleton):
//   K1  padding broadcast over dense region, 4x STG.128 per thread.
//   K2  idx-pattern blocks (leading) + red.v4 scatter with 2 independent
//       edge-chains per thread (MLP=2) to cover LDG latency.
// Tier 2: generic scalar path.
// ---------------------------------------------------------------------------

#define TB 256
#define IPT 4            // float4 stores per thread in K1

__device__ __forceinline__ void red_add_v4(float* dst, float4 r)
{
#if __CUDA_ARCH__ >= 900
    asm volatile("red.global.add.v4.f32 [%0], {%1, %2, %3, %4};"
                 :: "l"(dst), "f"(r.x), "f"(r.y), "f"(r.z), "f"(r.w)
                 : "memory");
#else
    atomicAdd(dst + 0, r.x); atomicAdd(dst + 1, r.y);
    atomicAdd(dst + 2, r.z); atomicAdd(dst + 3, r.w);
#endif
}

// ===========================================================================
// Tier 1 K1: padding broadcast init, IPT coalesced float4 stores per thread.
// Requires TB % D4 == 0 (D4 pow2 <= 256) so the column depends only on tid.
// ===========================================================================
__global__ void k_init4(float4* __restrict__ val4,
                        const float4* __restrict__ pad4,
                        long long V4, int D4)
{
    long long base = (long long)blockIdx.x * (TB * IPT) + threadIdx.x;
    float4 pv = __ldg(&pad4[(int)threadIdx.x & (D4 - 1)]);
    #pragma unroll
    for (int k = 0; k < IPT; k++) {
        long long v = base + (long long)k * TB;
        if (v < V4) val4[v] = pv;
    }
}

// ===========================================================================
// Tier 1 K2: idx pattern (leading blocks) + scatter, 2 edge-chunks/thread.
// Thread t handles work items t and t + halfTot (edges from the two halves
// of the edge array) -> two independent load chains in flight per thread.
// ===========================================================================
__global__ void k_idx_scatter(float* __restrict__ out, long long P,
                              const int* __restrict__ ei,
                              const float* __restrict__ pestat,
                              const float4* __restrict__ ea4,
                              const float4* __restrict__ w4,
                              float* __restrict__ val,
                              int E, int K, int s4, int sn,
                              int idxBlocks, int halfTot)
{
    const int tid = threadIdx.x;
    const int bid = blockIdx.x;

    if (bid < idxBlocks) {
        // ---- idx pattern, float4-vectorized (n % 4 == 0 by host guard) ----
        long long P4 = P >> 2;
        long long t = (long long)bid * TB + tid;
        if (t >= P4) return;
        long long q = t << 2;
        int nm1  = (1 << sn) - 1;
        long long nnm1 = ((long long)1 << (2 * sn)) - 1;
        int b   = (int)(q >> (2 * sn));
        int rem = (int)(q & nnm1);
        int i   = rem >> sn;
        int j   = rem & nm1;
        float rv = (float)((b << sn) + i);
        float cv = (float)((b << sn) + j);
        ((float4*)out)[t]       = make_float4(rv, rv, rv, rv);
        ((float4*)(out + P))[t] = make_float4(cv, cv + 1.f, cv + 2.f, cv + 3.f);
        return;
    }

    // ---- scatter with MLP=2 ----
    const int tot = E << s4;
    const int D4m = (1 << s4) - 1;
    const int nm1 = (1 << sn) - 1;
    int t0 = (bid - idxBlocks) * TB + tid;
    int t1 = t0 + halfTot;

    bool v0 = t0 < halfTot;            // first half item
    bool v1 = t1 < tot;                // second half item (tail-safe)

    int e0 = 0, c0 = 0, e1 = 0, c1 = 0;
    int u0 = 0, u1 = 0, r0 = 0, r1 = 0;
    float p0 = 0.f, p1 = 0.f;
    float4 a0, a1, w0, w1;

    // Issue both chains' loads back-to-back (independent -> overlap).
    if (v0) {
        e0 = t0 >> s4;  c0 = t0 & D4m;
        u0 = __ldg(&ei[e0]);
        r0 = __ldg(&ei[E + e0]) & nm1;
    }
    if (v1) {
        e1 = t1 >> s4;  c1 = t1 & D4m;
        u1 = __ldg(&ei[e1]);
        r1 = __ldg(&ei[E + e1]) & nm1;
    }
    if (v0) {
        p0 = __ldg(&pestat[(long long)e0 * K]);
        a0 = __ldg(&ea4[((long long)e0 << s4) + c0]);
        w0 = __ldg(&w4[c0]);
    }
    if (v1) {
        p1 = __ldg(&pestat[(long long)e1 * K]);
        a1 = __ldg(&ea4[((long long)e1 << s4) + c1]);
        w1 = __ldg(&w4[c1]);
    }

    if (v0) {
        float4 rr = make_float4(a0.x + p0 * w0.x, a0.y + p0 * w0.y,
                                a0.z + p0 * w0.z, a0.w + p0 * w0.w);
        long long slot = ((long long)u0 << sn) | r0;
        red_add_v4(val + (slot << (s4 + 2)) + (c0 << 2), rr);
    }
    if (v1) {
        float4 rr = make_float4(a1.x + p1 * w1.x, a1.y + p1 * w1.y,
                                a1.z + p1 * w1.z, a1.w + p1 * w1.w);
        long long slot = ((long long)u1 << sn) | r1;
        red_add_v4(val + (slot << (s4 + 2)) + (c1 << 2), rr);
    }
}

// ===========================================================================
// Tier 2: fully generic fallbacks.
// ===========================================================================
__global__ void k_init_fused_s(float* __restrict__ out, const float* __restrict__ pad,
                               long long P, int n, int D)
{
    long long totalI = P;
    long long tot = P + P * (long long)D;
    float* val = out + 2 * P;
    long long stride = (long long)gridDim.x * blockDim.x;
    for (long long t = (long long)blockIdx.x * blockDim.x + threadIdx.x;
         t < tot; t += stride) {
        if (t < totalI) {
            long long nn = (long long)n * n;
            int b   = (int)(t / nn);
            int rem = (int)(t - (long long)b * nn);
            int i   = rem / n;
            int j   = rem - i * n;
            out[t]     = (float)(b * n + i);
            out[P + t] = (float)(b * n + j);
        } else {
            long long v = t - totalI;
            val[v] = __ldg(&pad[(int)(v % D)]);
        }
    }
}

__global__ void k_scatter_s(const int* __restrict__ ei, const float* __restrict__ pestat,
                            const float* __restrict__ ea, const float* __restrict__ w,
                            float* __restrict__ val, int E, int K, int D, int n)
{
    long long tot = (long long)E * D;
    long long stride = (long long)gridDim.x * blockDim.x;
    for (long long t = (long long)blockIdx.x * blockDim.x + threadIdx.x;
         t < tot; t += stride) {
        int e = (int)(t / D);
        int d = (int)(t - (long long)e * D);
        int u = __ldg(&ei[e]);
        int v = __ldg(&ei[E + e]);
        int g  = u / n;
        int ru = u - g * n;
        int rv = v % n;
        float p = __ldg(&pestat[(long long)e * K]);
        float x = ea[(long long)e * D + d] + p * __ldg(&w[d]);
        long long base = (((long long)g * n + ru) * n + rv) * (long long)D + d;
        atomicAdd(val + base, x);
    }
}

// ===========================================================================

static inline bool is_pow2(int x) { return x > 0 && (x & (x - 1)) == 0; }
static inline int  ilog2(int x)   { int s = 0; while ((1 << s) < x) s++; return s; }
static inline int grid_for(long long work, int tb)
{
    long long g = (work + tb - 1) / tb;
    if (g > 1048576) g = 1048576;
    if (g < 1) g = 1;
    return (int)g;
}

extern "C" void kernel_launch(void* const* d_in, const int* in_sizes, int n_in,
                              void* d_out, int out_size)
{
    // metadata order: edge_index, pestat, edge_attr, batch, fc_w, padding
    const int*   ei     = (const int*)  d_in[0];
    const float* pestat = (const float*)d_in[1];
    const float* ea     = (const float*)d_in[2];
    const float* fc_w   = (const float*)d_in[4];
    const float* pad    = (const float*)d_in[5];

    const int E = in_sizes[0] / 2;
    const int K = in_sizes[1] / E;
    const int D = in_sizes[2] / E;
    const int N = in_sizes[3];                            // dense rows = B*n
    const long long P = (long long)out_size / (D + 2);    // slots = B*n*n
    const int n = (int)(P / N);

    float* out = (float*)d_out;
    float* val = out + 2 * P;
    const int D4 = D / 4;

    const bool pow2ok = (D % 4 == 0) && (n % 4 == 0) &&
                        is_pow2(n) && is_pow2(D4) && D4 <= 256 &&
                        ((long long)E * D4 < (1LL << 30));

    if (pow2ok) {
        const int sn = ilog2(n);
        const int s4 = ilog2(D4);
        const long long V4 = P * (long long)D4;

        // K1: padding init, IPT float4 stores per thread.
        long long initBlocks = (V4 + (long long)TB * IPT - 1) / ((long long)TB * IPT);
        k_init4<<<(int)initBlocks, TB>>>((float4*)val, (const float4*)pad,
                                         V4, D4);

        // K2: idx pattern (leading) + scatter with 2 items per thread.
        const int tot     = E << s4;
        const int halfTot = (tot + 1) / 2;
        const int idxBlocks  = (int)(((P >> 2) + TB - 1) / TB);
        const int scatBlocks = (halfTot + TB - 1) / TB;
        k_idx_scatter<<<idxBlocks + scatBlocks, TB>>>(out, P, ei, pestat,
                                                      (const float4*)ea,
                                                      (const float4*)fc_w,
                                                      val, E, K, s4, sn,
                                                      idxBlocks, halfTot);
    } else {
        long long tot = P + P * (long long)D;
        k_init_fused_s<<<grid_for(tot, TB), TB>>>(out, pad, P, n, D);
        long long st = (long long)E * D;
        k_scatter_s<<<grid_for(st, TB), TB>>>(ei, pestat, ea, fc_w, val,
                                              E, K, D, n);
    }
}